// round 7
// baseline (speedup 1.0000x reference)
#include <cuda_runtime.h>
#include <cuda_bf16.h>
#include <cstddef>

#define NN 50000
#define EE 800000
#define NF 256
#define HH 128
#define LL 3
#define NEG_SLOPE 0.01f
#define NBLK 196   // ceil(NN/256)

// ---------------- scratch (no allocations allowed) ----------------
__device__ __nv_bfloat16 g_h0b [(size_t)NN * HH];  // projection output
__device__ __nv_bfloat16 g_hb  [(size_t)NN * HH];  // current hidden h
__device__ __nv_bfloat16 g_msgb[(size_t)NN * HH];  // h*invdeg messages
__device__ __nv_bfloat16 g_aggb[(size_t)NN * HH];  // aggregation buffer
__device__ float g_invdeg[NN];
__device__ float g_colsum[HH * (LL + 1)];
__device__ int   g_cnt[NN];
__device__ int   g_pos[NN];
__device__ int   g_rowptr[NN + 1];
__device__ int   g_col[EE];
__device__ int   g_bsum[NBLK];
__device__ int   g_boff[NBLK];

// ---------------- helpers ----------------
__device__ __forceinline__ unsigned f2tf32(float x) {
    unsigned u;
    asm("cvt.rna.tf32.f32 %0, %1;" : "=r"(u) : "f"(x));
    return u;
}

__device__ __forceinline__ unsigned packbf2(float lo, float hi) {
    __nv_bfloat162 b = __floats2bfloat162_rn(lo, hi);
    return *reinterpret_cast<unsigned*>(&b);
}

__device__ __forceinline__ void mma_tf32(float* d, const unsigned* a, const unsigned* b) {
    asm volatile(
        "mma.sync.aligned.m16n8k8.row.col.f32.tf32.tf32.f32 "
        "{%0,%1,%2,%3}, {%4,%5,%6,%7}, {%8,%9}, {%0,%1,%2,%3};\n"
        : "+f"(d[0]), "+f"(d[1]), "+f"(d[2]), "+f"(d[3])
        : "r"(a[0]), "r"(a[1]), "r"(a[2]), "r"(a[3]), "r"(b[0]), "r"(b[1]));
}

__device__ __forceinline__ void mma_bf16(float* d, const unsigned* a, const unsigned* b) {
    asm volatile(
        "mma.sync.aligned.m16n8k16.row.col.f32.bf16.bf16.f32 "
        "{%0,%1,%2,%3}, {%4,%5,%6,%7}, {%8,%9}, {%0,%1,%2,%3};\n"
        : "+f"(d[0]), "+f"(d[1]), "+f"(d[2]), "+f"(d[3])
        : "r"(a[0]), "r"(a[1]), "r"(a[2]), "r"(a[3]), "r"(b[0]), "r"(b[1]));
}

__device__ __forceinline__ void acc_bf16row(float4& acc, const __nv_bfloat16* p) {
    uint2 r = *reinterpret_cast<const uint2*>(p);
    __nv_bfloat162 b0 = *reinterpret_cast<const __nv_bfloat162*>(&r.x);
    __nv_bfloat162 b1 = *reinterpret_cast<const __nv_bfloat162*>(&r.y);
    float2 f0 = __bfloat1622float2(b0);
    float2 f1 = __bfloat1622float2(b1);
    acc.x += f0.x; acc.y += f0.y; acc.z += f1.x; acc.w += f1.y;
}

// ---------------- init ----------------
__global__ void init_kernel(const float* __restrict__ degree, float* __restrict__ invdeg,
                            int* __restrict__ cnt, int* __restrict__ pos,
                            float* __restrict__ cs) {
    int i = blockIdx.x * blockDim.x + threadIdx.x;
    if (i < NN) {
        invdeg[i] = 1.0f / degree[i];
        cnt[i] = 0;
        pos[i] = 0;
    }
    if (i < HH * (LL + 1)) cs[i] = 0.f;
}

// ---------------- CSR build ----------------
__global__ void hist_kernel(const int* __restrict__ dst, int* __restrict__ cnt) {
    int e = blockIdx.x * blockDim.x + threadIdx.x;
    if (e < EE) atomicAdd(&cnt[dst[e]], 1);
}

// block-local exclusive prescan of cnt into rowptr; block total -> bsum
__global__ void scan1_kernel(const int* __restrict__ cnt, int* __restrict__ rowptr,
                             int* __restrict__ bsum) {
    __shared__ int ws[8];
    int tid = threadIdx.x, lane = tid & 31, wid = tid >> 5;
    int i = blockIdx.x * 256 + tid;
    int v = (i < NN) ? cnt[i] : 0;
    int x = v;
#pragma unroll
    for (int off = 1; off < 32; off <<= 1) {
        int y = __shfl_up_sync(0xffffffffu, x, off);
        if (lane >= off) x += y;
    }
    if (lane == 31) ws[wid] = x;
    __syncthreads();
    if (wid == 0 && lane < 8) {
        int s = ws[lane];
#pragma unroll
        for (int off = 1; off < 8; off <<= 1) {
            int y = __shfl_up_sync(0x000000ffu, s, off);
            if (lane >= off) s += y;
        }
        ws[lane] = s;
    }
    __syncthreads();
    int woff = wid ? ws[wid - 1] : 0;
    if (i < NN) rowptr[i] = woff + x - v;
    if (tid == 255) bsum[blockIdx.x] = woff + x;
}

// scan of NBLK block sums -> boff ; total -> rowptr[NN]
__global__ void scan2_kernel(const int* __restrict__ bsum, int* __restrict__ boff,
                             int* __restrict__ rowptr) {
    __shared__ int ws[8];
    int tid = threadIdx.x, lane = tid & 31, wid = tid >> 5;
    int v = (tid < NBLK) ? bsum[tid] : 0;
    int x = v;
#pragma unroll
    for (int off = 1; off < 32; off <<= 1) {
        int y = __shfl_up_sync(0xffffffffu, x, off);
        if (lane >= off) x += y;
    }
    if (lane == 31) ws[wid] = x;
    __syncthreads();
    if (wid == 0 && lane < 8) {
        int s = ws[lane];
#pragma unroll
        for (int off = 1; off < 8; off <<= 1) {
            int y = __shfl_up_sync(0x000000ffu, s, off);
            if (lane >= off) s += y;
        }
        ws[lane] = s;
    }
    __syncthreads();
    int woff = wid ? ws[wid - 1] : 0;
    if (tid < NBLK) boff[tid] = woff + x - v;
    if (tid == 255) rowptr[NN] = woff + x;
}

__global__ void scan3_kernel(int* __restrict__ rowptr, const int* __restrict__ boff) {
    int i = blockIdx.x * 256 + threadIdx.x;
    if (i < NN) rowptr[i] += boff[blockIdx.x];
}

__global__ void fill_kernel(const int* __restrict__ src, const int* __restrict__ dst,
                            const int* __restrict__ rowptr, int* __restrict__ pos,
                            int* __restrict__ col) {
    int e = blockIdx.x * blockDim.x + threadIdx.x;
    if (e >= EE) return;
    int d = dst[e];
    int p = atomicAdd(&pos[d], 1);
    col[rowptr[d] + p] = src[e];
}

// ---------------- gather ----------------
// FUSION: acc = sum h0b[u]; write hb = bf16(acc), msgb = bf16(acc*invdeg[v]).
// !FUSION: acc = f32(hb[v]) + sum msgb[u]; write aggb = bf16(acc).
template <bool FUSION>
__global__ __launch_bounds__(256)
void gather_kernel(const __nv_bfloat16* __restrict__ msg,
                   const __nv_bfloat16* __restrict__ base,
                   __nv_bfloat16* __restrict__ out1, __nv_bfloat16* __restrict__ out2,
                   const float* __restrict__ invdeg,
                   const int* __restrict__ rowptr, const int* __restrict__ col) {
    int node = (blockIdx.x * blockDim.x + threadIdx.x) >> 5;
    int lane = threadIdx.x & 31;
    if (node >= NN) return;
    int s0 = __ldg(rowptr + node), s1 = __ldg(rowptr + node + 1);

    float4 acc = make_float4(0.f, 0.f, 0.f, 0.f);
    if (!FUSION)
        acc_bf16row(acc, base + (size_t)node * HH + lane * 4);

    const __nv_bfloat16* mbase = msg + lane * 4;
    int e = s0;
    for (; e + 3 < s1; e += 4) {
        int u0 = __ldg(col + e),     u1 = __ldg(col + e + 1);
        int u2 = __ldg(col + e + 2), u3 = __ldg(col + e + 3);
        acc_bf16row(acc, mbase + (size_t)u0 * HH);
        acc_bf16row(acc, mbase + (size_t)u1 * HH);
        acc_bf16row(acc, mbase + (size_t)u2 * HH);
        acc_bf16row(acc, mbase + (size_t)u3 * HH);
    }
    for (; e < s1; e++) {
        int u0 = __ldg(col + e);
        acc_bf16row(acc, mbase + (size_t)u0 * HH);
    }

    uint2 p1;
    p1.x = packbf2(acc.x, acc.y);
    p1.y = packbf2(acc.z, acc.w);
    *reinterpret_cast<uint2*>(out1 + (size_t)node * HH + lane * 4) = p1;
    if (FUSION) {
        float iv = __ldg(invdeg + node);
        uint2 p2;
        p2.x = packbf2(acc.x * iv, acc.y * iv);
        p2.y = packbf2(acc.z * iv, acc.w * iv);
        *reinterpret_cast<uint2*>(out2 + (size_t)node * HH + lane * 4) = p2;
    }
}

// ---------------- projection GEMM (tf32): h0b = bf16(A @ W + b), colsum[0:HH] --------
__global__ __launch_bounds__(256, 2)
void gemm_proj(const float* __restrict__ A, const float* __restrict__ W,
               const float* __restrict__ bias, __nv_bfloat16* __restrict__ Cb,
               float* __restrict__ colsum) {
    __shared__ unsigned As[128][36];
    __shared__ unsigned Ws[32][132];
    __shared__ float colsm[HH];

    const int tid = threadIdx.x;
    const int warp = tid >> 5, lane = tid & 31;
    const int wm = warp & 3, wn = warp >> 2;
    const int g = lane >> 2, t = lane & 3;
    const int row0 = blockIdx.x * 128;

    float acc[2][8][4];
#pragma unroll
    for (int mt = 0; mt < 2; mt++)
#pragma unroll
        for (int nt = 0; nt < 8; nt++)
#pragma unroll
            for (int r = 0; r < 4; r++) acc[mt][nt][r] = 0.f;

    if (tid < HH) colsm[tid] = 0.f;

    for (int k0 = 0; k0 < NF; k0 += 32) {
#pragma unroll
        for (int i = 0; i < 4; i++) {
            int idx = tid + i * 256;
            int r = idx >> 3, q = idx & 7;
            float4 v = make_float4(0.f, 0.f, 0.f, 0.f);
            if (row0 + r < NN)
                v = *reinterpret_cast<const float4*>(A + (size_t)(row0 + r) * NF + k0 + q * 4);
            unsigned* p = &As[r][q * 4];
            p[0] = f2tf32(v.x); p[1] = f2tf32(v.y); p[2] = f2tf32(v.z); p[3] = f2tf32(v.w);
        }
#pragma unroll
        for (int i = 0; i < 4; i++) {
            int idx = tid + i * 256;
            int kk = idx >> 5, n4 = idx & 31;
            float4 w = *reinterpret_cast<const float4*>(W + (size_t)(k0 + kk) * HH + n4 * 4);
            unsigned* p = &Ws[kk][n4 * 4];
            p[0] = f2tf32(w.x); p[1] = f2tf32(w.y); p[2] = f2tf32(w.z); p[3] = f2tf32(w.w);
        }
        __syncthreads();

#pragma unroll
        for (int k8 = 0; k8 < 4; k8++) {
            const int kk = k8 * 8;
            unsigned a[2][4], b[8][2];
#pragma unroll
            for (int mt = 0; mt < 2; mt++) {
                int r = wm * 32 + mt * 16;
                a[mt][0] = As[r + g][kk + t];
                a[mt][1] = As[r + g + 8][kk + t];
                a[mt][2] = As[r + g][kk + t + 4];
                a[mt][3] = As[r + g + 8][kk + t + 4];
            }
#pragma unroll
            for (int nt = 0; nt < 8; nt++) {
                int n = wn * 64 + nt * 8;
                b[nt][0] = Ws[kk + t][n + g];
                b[nt][1] = Ws[kk + t + 4][n + g];
            }
#pragma unroll
            for (int mt = 0; mt < 2; mt++)
#pragma unroll
                for (int nt = 0; nt < 8; nt++)
                    mma_tf32(acc[mt][nt], a[mt], b[nt]);
        }
        __syncthreads();
    }

    float csum[8][2];
#pragma unroll
    for (int nt = 0; nt < 8; nt++) { csum[nt][0] = 0.f; csum[nt][1] = 0.f; }

#pragma unroll
    for (int mt = 0; mt < 2; mt++) {
        int rr[2];
        rr[0] = row0 + wm * 32 + mt * 16 + g;
        rr[1] = rr[0] + 8;
#pragma unroll
        for (int half = 0; half < 2; half++) {
            int r = rr[half];
            if (r >= NN) continue;
#pragma unroll
            for (int nt = 0; nt < 8; nt++) {
                int coln = wn * 64 + nt * 8 + 2 * t;
                float b0 = __ldg(bias + coln), b1 = __ldg(bias + coln + 1);
                float x0 = acc[mt][nt][half * 2 + 0] + b0;
                float x1 = acc[mt][nt][half * 2 + 1] + b1;
                csum[nt][0] += x0; csum[nt][1] += x1;
                *reinterpret_cast<unsigned*>(Cb + (size_t)r * HH + coln) = packbf2(x0, x1);
            }
        }
    }

    __syncthreads();
#pragma unroll
    for (int nt = 0; nt < 8; nt++) {
#pragma unroll
        for (int c = 0; c < 2; c++) {
            float s = csum[nt][c];
            s += __shfl_xor_sync(0xffffffffu, s, 4);
            s += __shfl_xor_sync(0xffffffffu, s, 8);
            s += __shfl_xor_sync(0xffffffffu, s, 16);
            if (g == 0) atomicAdd(&colsm[wn * 64 + nt * 8 + 2 * t + c], s);
        }
    }
    __syncthreads();
    if (tid < HH) atomicAdd(&colsum[tid], colsm[tid]);
}

// ---------------- layer GEMM (bf16 A, bf16 MMA) ----------------
// h = leaky(aggb @ W + b). LAST: colsum only. else: hb = bf16(h), msgb = bf16(h*invdeg).
template <bool LAST>
__global__ __launch_bounds__(256, 2)
void gemm_layer(const __nv_bfloat16* __restrict__ A, const float* __restrict__ W,
                const float* __restrict__ bias, __nv_bfloat16* __restrict__ Hb,
                __nv_bfloat16* __restrict__ Mb, const float* __restrict__ invdeg,
                float* __restrict__ colsum, int cs_off) {
    __shared__ unsigned As2[128][18];   // 16 uints (32 bf16) per row + pad
    __shared__ unsigned Ws2[16][132];   // k-pairs x n
    __shared__ float colsm[HH];

    const int tid = threadIdx.x;
    const int warp = tid >> 5, lane = tid & 31;
    const int wm = warp & 3, wn = warp >> 2;
    const int g = lane >> 2, t = lane & 3;
    const int row0 = blockIdx.x * 128;

    float acc[2][8][4];
#pragma unroll
    for (int mt = 0; mt < 2; mt++)
#pragma unroll
        for (int nt = 0; nt < 8; nt++)
#pragma unroll
            for (int r = 0; r < 4; r++) acc[mt][nt][r] = 0.f;

    if (tid < HH) colsm[tid] = 0.f;

    for (int k0 = 0; k0 < HH; k0 += 32) {
        // A tile: 128 rows x 32 bf16 = 1024 uint2, 4 per thread
#pragma unroll
        for (int i = 0; i < 4; i++) {
            int idx = tid + i * 256;
            int r = idx >> 3, j = idx & 7;
            uint2 u = make_uint2(0u, 0u);
            if (row0 + r < NN)
                u = *reinterpret_cast<const uint2*>(A + (size_t)(row0 + r) * HH + k0 + j * 4);
            As2[r][2 * j]     = u.x;
            As2[r][2 * j + 1] = u.y;
        }
        // W tile: pack pairs along k: Ws2[k2][n] = (W[k0+2k2][n], W[k0+2k2+1][n])
#pragma unroll
        for (int i = 0; i < 2; i++) {
            int idx = tid + i * 256;
            int k2 = idx >> 5, n4 = idx & 31;
            float4 w0 = *reinterpret_cast<const float4*>(W + (size_t)(k0 + 2 * k2) * HH + n4 * 4);
            float4 w1 = *reinterpret_cast<const float4*>(W + (size_t)(k0 + 2 * k2 + 1) * HH + n4 * 4);
            unsigned* p = &Ws2[k2][n4 * 4];
            p[0] = packbf2(w0.x, w1.x);
            p[1] = packbf2(w0.y, w1.y);
            p[2] = packbf2(w0.z, w1.z);
            p[3] = packbf2(w0.w, w1.w);
        }
        __syncthreads();

#pragma unroll
        for (int ks = 0; ks < 2; ks++) {
            const int kk2 = ks * 8;
            unsigned a[2][4], b[8][2];
#pragma unroll
            for (int mt = 0; mt < 2; mt++) {
                int r = wm * 32 + mt * 16;
                a[mt][0] = As2[r + g][kk2 + t];
                a[mt][1] = As2[r + g + 8][kk2 + t];
                a[mt][2] = As2[r + g][kk2 + t + 4];
                a[mt][3] = As2[r + g + 8][kk2 + t + 4];
            }
#pragma unroll
            for (int nt = 0; nt < 8; nt++) {
                int n = wn * 64 + nt * 8;
                b[nt][0] = Ws2[kk2 + t][n + g];
                b[nt][1] = Ws2[kk2 + t + 4][n + g];
            }
#pragma unroll
            for (int mt = 0; mt < 2; mt++)
#pragma unroll
                for (int nt = 0; nt < 8; nt++)
                    mma_bf16(acc[mt][nt], a[mt], b[nt]);
        }
        __syncthreads();
    }

    float csum[8][2];
#pragma unroll
    for (int nt = 0; nt < 8; nt++) { csum[nt][0] = 0.f; csum[nt][1] = 0.f; }

#pragma unroll
    for (int mt = 0; mt < 2; mt++) {
        int rr[2];
        rr[0] = row0 + wm * 32 + mt * 16 + g;
        rr[1] = rr[0] + 8;
#pragma unroll
        for (int half = 0; half < 2; half++) {
            int r = rr[half];
            if (r >= NN) continue;
            float iv = LAST ? 1.0f : __ldg(invdeg + r);
#pragma unroll
            for (int nt = 0; nt < 8; nt++) {
                int coln = wn * 64 + nt * 8 + 2 * t;
                float b0 = __ldg(bias + coln), b1 = __ldg(bias + coln + 1);
                float x0 = acc[mt][nt][half * 2 + 0] + b0;
                float x1 = acc[mt][nt][half * 2 + 1] + b1;
                x0 = (x0 >= 0.f) ? x0 : NEG_SLOPE * x0;
                x1 = (x1 >= 0.f) ? x1 : NEG_SLOPE * x1;
                csum[nt][0] += x0; csum[nt][1] += x1;
                if (!LAST) {
                    *reinterpret_cast<unsigned*>(Hb + (size_t)r * HH + coln) = packbf2(x0, x1);
                    *reinterpret_cast<unsigned*>(Mb + (size_t)r * HH + coln) =
                        packbf2(x0 * iv, x1 * iv);
                }
            }
        }
    }

    __syncthreads();
#pragma unroll
    for (int nt = 0; nt < 8; nt++) {
#pragma unroll
        for (int c = 0; c < 2; c++) {
            float s = csum[nt][c];
            s += __shfl_xor_sync(0xffffffffu, s, 4);
            s += __shfl_xor_sync(0xffffffffu, s, 8);
            s += __shfl_xor_sync(0xffffffffu, s, 16);
            if (g == 0) atomicAdd(&colsm[wn * 64 + nt * 8 + 2 * t + c], s);
        }
    }
    __syncthreads();
    if (tid < HH) atomicAdd(&colsum[cs_off + tid], colsm[tid]);
}

// ---------------- final: column means -> Wpred -> Wcls -> softmax ----------------
__global__ void final_kernel(const float* __restrict__ colsum,
                             const float* __restrict__ Wpred, const float* __restrict__ bpred,
                             const float* __restrict__ Wcls, const float* __restrict__ bcls,
                             float* __restrict__ out) {
    __shared__ float cm[HH * (LL + 1)];
    __shared__ float gsh[HH];
    int tid = threadIdx.x;  // 128 threads
    for (int t = tid; t < HH * (LL + 1); t += 128) cm[t] = colsum[t] * (1.0f / (float)NN);
    __syncthreads();
    float g = bpred[tid];
    for (int k = 0; k < HH * (LL + 1); k++) g += cm[k] * Wpred[(size_t)k * HH + tid];
    gsh[tid] = g;
    __syncthreads();
    if (tid == 0) {
        float l0 = bcls[0], l1 = bcls[1];
        for (int j = 0; j < HH; j++) {
            l0 += gsh[j] * Wcls[j * 2 + 0];
            l1 += gsh[j] * Wcls[j * 2 + 1];
        }
        float m = fmaxf(l0, l1);
        float e0 = expf(l0 - m), e1 = expf(l1 - m);
        float inv = 1.0f / (e0 + e1);
        out[0] = e0 * inv;
        out[1] = e1 * inv;
    }
}

// ---------------- launch ----------------
extern "C" void kernel_launch(void* const* d_in, const int* in_sizes, int n_in,
                              void* d_out, int out_size) {
    const float* node_feat = (const float*)d_in[0];
    const float* degree    = (const float*)d_in[3];
    const float* Wn        = (const float*)d_in[4];
    const float* bn        = (const float*)d_in[5];
    const float* Wgcn      = (const float*)d_in[8];
    const float* bgcn      = (const float*)d_in[9];
    const float* Wpred     = (const float*)d_in[10];
    const float* bpred     = (const float*)d_in[11];
    const float* Wcls      = (const float*)d_in[12];
    const float* bcls      = (const float*)d_in[13];
    const int*   src       = (const int*)d_in[14];
    const int*   dst       = (const int*)d_in[15];
    float* out = (float*)d_out;

    float *p_inv, *p_cs;
    __nv_bfloat16 *p_h0b, *p_hb, *p_msgb, *p_aggb;
    int *p_cnt, *p_pos, *p_rp, *p_col, *p_bsum, *p_boff;
    cudaGetSymbolAddress((void**)&p_h0b,  g_h0b);
    cudaGetSymbolAddress((void**)&p_hb,   g_hb);
    cudaGetSymbolAddress((void**)&p_msgb, g_msgb);
    cudaGetSymbolAddress((void**)&p_aggb, g_aggb);
    cudaGetSymbolAddress((void**)&p_inv,  g_invdeg);
    cudaGetSymbolAddress((void**)&p_cs,   g_colsum);
    cudaGetSymbolAddress((void**)&p_cnt,  g_cnt);
    cudaGetSymbolAddress((void**)&p_pos,  g_pos);
    cudaGetSymbolAddress((void**)&p_rp,   g_rowptr);
    cudaGetSymbolAddress((void**)&p_col,  g_col);
    cudaGetSymbolAddress((void**)&p_bsum, g_bsum);
    cudaGetSymbolAddress((void**)&p_boff, g_boff);

    const int gemm_blocks = (NN + 127) / 128;        // 391
    const int edge_blocks = (EE + 255) / 256;        // 3125
    const int node_blocks = NBLK;                    // 196
    const int gath_blocks = (NN * 32 + 255) / 256;   // 6250

    // 1) init counters / invdeg / colsum
    init_kernel<<<node_blocks, 256>>>(degree, p_inv, p_cnt, p_pos, p_cs);

    // 2) CSR build (dst-major), multi-block scan
    hist_kernel<<<edge_blocks, 256>>>(dst, p_cnt);
    scan1_kernel<<<node_blocks, 256>>>(p_cnt, p_rp, p_bsum);
    scan2_kernel<<<1, 256>>>(p_bsum, p_boff, p_rp);
    scan3_kernel<<<node_blocks, 256>>>(p_rp, p_boff);
    fill_kernel<<<edge_blocks, 256>>>(src, dst, p_rp, p_pos, p_col);

    // 3) projection: h0b = bf16(node_feat @ Wn + bn) ; colsum[0:128]
    gemm_proj<<<gemm_blocks, 256>>>(node_feat, Wn, bn, p_h0b, p_cs);

    // 4) fusion: hb[v] = sum h0b[u] ; msgb[v] = bf16(sum * invdeg[v])
    gather_kernel<true><<<gath_blocks, 256>>>(p_h0b, nullptr, p_hb, p_msgb,
                                              p_inv, p_rp, p_col);

    // 5) 3 GCN layers
    for (int l = 0; l < LL; l++) {
        // aggb[v] = hb[v] + sum msgb[u]
        gather_kernel<false><<<gath_blocks, 256>>>(p_msgb, p_hb, p_aggb, nullptr,
                                                   nullptr, p_rp, p_col);
        // h = leaky(aggb @ Wgcn + bgcn); hb/msgb updated (last: colsum only)
        if (l < LL - 1)
            gemm_layer<false><<<gemm_blocks, 256>>>(p_aggb, Wgcn, bgcn, p_hb, p_msgb,
                                                    p_inv, p_cs, (l + 1) * HH);
        else
            gemm_layer<true><<<gemm_blocks, 256>>>(p_aggb, Wgcn, bgcn, nullptr, nullptr,
                                                   nullptr, p_cs, (l + 1) * HH);
    }

    // 6) readout
    final_kernel<<<1, 128>>>(p_cs, Wpred, bpred, Wcls, bcls, out);
}

// round 8
// speedup vs baseline: 1.4474x; 1.4474x over previous
#include <cuda_runtime.h>
#include <cuda_bf16.h>
#include <cstddef>

#define NN 50000
#define EE 800000
#define NF 256
#define HH 128
#define LL 3
#define NEG_SLOPE 0.01f
#define NBLK 196   // ceil(NN/256)

// ---------------- scratch (no allocations allowed) ----------------
__device__ float         g_cur[(size_t)NN * HH];   // current hidden h (fp32)
__device__ float         g_agg[(size_t)NN * HH];   // aggregation buffer (fp32)
__device__ __nv_bfloat16 g_h0b[(size_t)NN * HH];   // projection output (bf16)
__device__ __nv_bfloat16 g_msgb[(size_t)NN * HH];  // h*invdeg messages (bf16)
__device__ float g_invdeg[NN];
__device__ float g_colsum[HH * (LL + 1)];
__device__ int   g_cnt[NN];
__device__ int   g_rank[EE];
__device__ int   g_rowptr[NN + 1];
__device__ int   g_col[EE];                // src node per dst-sorted edge
__device__ int   g_bsum[NBLK];
__device__ int   g_boff[NBLK];

// ---------------- helpers ----------------
__device__ __forceinline__ unsigned f2tf32(float x) {
    unsigned u;
    asm("cvt.rna.tf32.f32 %0, %1;" : "=r"(u) : "f"(x));
    return u;
}

__device__ __forceinline__ void mma_tf32(float* d, const unsigned* a, const unsigned* b) {
    asm volatile(
        "mma.sync.aligned.m16n8k8.row.col.f32.tf32.tf32.f32 "
        "{%0,%1,%2,%3}, {%4,%5,%6,%7}, {%8,%9}, {%0,%1,%2,%3};\n"
        : "+f"(d[0]), "+f"(d[1]), "+f"(d[2]), "+f"(d[3])
        : "r"(a[0]), "r"(a[1]), "r"(a[2]), "r"(a[3]), "r"(b[0]), "r"(b[1]));
}

__device__ __forceinline__ void acc_bf16row(float4& acc, const __nv_bfloat16* p) {
    uint2 r = *reinterpret_cast<const uint2*>(p);
    __nv_bfloat162 b0 = *reinterpret_cast<const __nv_bfloat162*>(&r.x);
    __nv_bfloat162 b1 = *reinterpret_cast<const __nv_bfloat162*>(&r.y);
    float2 f0 = __bfloat1622float2(b0);
    float2 f1 = __bfloat1622float2(b1);
    acc.x += f0.x; acc.y += f0.y; acc.z += f1.x; acc.w += f1.y;
}

// ---------------- init: counters + colsum + invdeg ----------------
__global__ void init_kernel(const float* __restrict__ degree, float* __restrict__ invdeg,
                            int* __restrict__ cnt, float* __restrict__ cs) {
    int i = blockIdx.x * blockDim.x + threadIdx.x;
    if (i < NN) {
        invdeg[i] = 1.0f / degree[i];
        cnt[i] = 0;
    }
    if (i < HH * (LL + 1)) cs[i] = 0.f;
}

// ---------------- CSR build ----------------
// hist: count per dst AND record each edge's rank within its dst bucket.
__global__ void hist_kernel(const int* __restrict__ dst, int* __restrict__ cnt,
                            int* __restrict__ rank) {
    int e = blockIdx.x * blockDim.x + threadIdx.x;
    if (e < EE) rank[e] = atomicAdd(&cnt[dst[e]], 1);
}

// block-local exclusive prescan of cnt into rowptr; block total -> bsum
__global__ void scan1_kernel(const int* __restrict__ cnt, int* __restrict__ rowptr,
                             int* __restrict__ bsum) {
    __shared__ int ws[8];
    int tid = threadIdx.x, lane = tid & 31, wid = tid >> 5;
    int i = blockIdx.x * 256 + tid;
    int v = (i < NN) ? cnt[i] : 0;
    int x = v;
#pragma unroll
    for (int off = 1; off < 32; off <<= 1) {
        int y = __shfl_up_sync(0xffffffffu, x, off);
        if (lane >= off) x += y;
    }
    if (lane == 31) ws[wid] = x;
    __syncthreads();
    if (wid == 0 && lane < 8) {
        int s = ws[lane];
#pragma unroll
        for (int off = 1; off < 8; off <<= 1) {
            int y = __shfl_up_sync(0x000000ffu, s, off);
            if (lane >= off) s += y;
        }
        ws[lane] = s;
    }
    __syncthreads();
    int woff = wid ? ws[wid - 1] : 0;
    if (i < NN) rowptr[i] = woff + x - v;
    if (tid == 255) bsum[blockIdx.x] = woff + x;
}

// scan of NBLK block sums -> boff ; total -> rowptr[NN]
__global__ void scan2_kernel(const int* __restrict__ bsum, int* __restrict__ boff,
                             int* __restrict__ rowptr) {
    __shared__ int ws[8];
    int tid = threadIdx.x, lane = tid & 31, wid = tid >> 5;
    int v = (tid < NBLK) ? bsum[tid] : 0;
    int x = v;
#pragma unroll
    for (int off = 1; off < 32; off <<= 1) {
        int y = __shfl_up_sync(0xffffffffu, x, off);
        if (lane >= off) x += y;
    }
    if (lane == 31) ws[wid] = x;
    __syncthreads();
    if (wid == 0 && lane < 8) {
        int s = ws[lane];
#pragma unroll
        for (int off = 1; off < 8; off <<= 1) {
            int y = __shfl_up_sync(0x000000ffu, s, off);
            if (lane >= off) s += y;
        }
        ws[lane] = s;
    }
    __syncthreads();
    int woff = wid ? ws[wid - 1] : 0;
    if (tid < NBLK) boff[tid] = woff + x - v;
    if (tid == 255) rowptr[NN] = woff + x;
}

__global__ void scan3_kernel(int* __restrict__ rowptr, const int* __restrict__ boff) {
    int i = blockIdx.x * 256 + threadIdx.x;
    if (i < NN) rowptr[i] += boff[blockIdx.x];
}

// fill: no atomics — rank was captured in hist.
__global__ void fill_kernel(const int* __restrict__ src, const int* __restrict__ dst,
                            const int* __restrict__ rowptr, const int* __restrict__ rank,
                            int* __restrict__ col) {
    int e = blockIdx.x * blockDim.x + threadIdx.x;
    if (e >= EE) return;
    col[rowptr[dst[e]] + rank[e]] = src[e];
}

// ---------------- gather (bf16 messages): out[v] = (base[v]?) + sum msg[u] -------------
// OUTB16: additionally write outb[v] = out[v]*invdeg[v] as bf16.
template <bool ADDBASE, bool OUTB16>
__global__ __launch_bounds__(256)
void gather_kernel(const __nv_bfloat16* __restrict__ msg, const float* __restrict__ base,
                   float* __restrict__ out, __nv_bfloat16* __restrict__ outb,
                   const float* __restrict__ invdeg,
                   const int* __restrict__ rowptr, const int* __restrict__ col) {
    int node = (blockIdx.x * blockDim.x + threadIdx.x) >> 5;
    int lane = threadIdx.x & 31;
    if (node >= NN) return;
    int s0 = __ldg(rowptr + node), s1 = __ldg(rowptr + node + 1);

    float4 acc;
    if (ADDBASE)
        acc = *reinterpret_cast<const float4*>(base + (size_t)node * HH + lane * 4);
    else
        acc = make_float4(0.f, 0.f, 0.f, 0.f);

    const __nv_bfloat16* mbase = msg + lane * 4;
    int e = s0;
    for (; e + 3 < s1; e += 4) {
        int u0 = __ldg(col + e),     u1 = __ldg(col + e + 1);
        int u2 = __ldg(col + e + 2), u3 = __ldg(col + e + 3);
        acc_bf16row(acc, mbase + (size_t)u0 * HH);
        acc_bf16row(acc, mbase + (size_t)u1 * HH);
        acc_bf16row(acc, mbase + (size_t)u2 * HH);
        acc_bf16row(acc, mbase + (size_t)u3 * HH);
    }
    for (; e < s1; e++) {
        int u0 = __ldg(col + e);
        acc_bf16row(acc, mbase + (size_t)u0 * HH);
    }

    *reinterpret_cast<float4*>(out + (size_t)node * HH + lane * 4) = acc;
    if (OUTB16) {
        float iv = __ldg(invdeg + node);
        __nv_bfloat162 o0 = __floats2bfloat162_rn(acc.x * iv, acc.y * iv);
        __nv_bfloat162 o1 = __floats2bfloat162_rn(acc.z * iv, acc.w * iv);
        uint2 packed;
        packed.x = *reinterpret_cast<unsigned*>(&o0);
        packed.y = *reinterpret_cast<unsigned*>(&o1);
        *reinterpret_cast<uint2*>(outb + (size_t)node * HH + lane * 4) = packed;
    }
}

// ---------------- tf32 tensor-core GEMM ----------------
// OUTMODE: 0 = colsum only; 1 = bf16 unscaled to Cb; 2 = fp32 to C + bf16*invdeg to Cb.
template <int K, bool LEAKY, int OUTMODE>
__global__ __launch_bounds__(256, 2)
void gemm_tc(const float* __restrict__ A, const float* __restrict__ W,
             const float* __restrict__ bias, float* __restrict__ C,
             __nv_bfloat16* __restrict__ Cb, const float* __restrict__ invdeg,
             float* __restrict__ colsum, int cs_off) {
    __shared__ unsigned As[128][36];
    __shared__ unsigned Ws[32][132];
    __shared__ float colsm[HH];

    const int tid = threadIdx.x;
    const int warp = tid >> 5, lane = tid & 31;
    const int wm = warp & 3, wn = warp >> 2;
    const int g = lane >> 2, t = lane & 3;
    const int row0 = blockIdx.x * 128;

    float acc[2][8][4];
#pragma unroll
    for (int mt = 0; mt < 2; mt++)
#pragma unroll
        for (int nt = 0; nt < 8; nt++)
#pragma unroll
            for (int r = 0; r < 4; r++) acc[mt][nt][r] = 0.f;

    if (tid < HH) colsm[tid] = 0.f;

    for (int k0 = 0; k0 < K; k0 += 32) {
#pragma unroll
        for (int i = 0; i < 4; i++) {
            int idx = tid + i * 256;
            int r = idx >> 3, q = idx & 7;
            float4 v = make_float4(0.f, 0.f, 0.f, 0.f);
            if (row0 + r < NN)
                v = *reinterpret_cast<const float4*>(A + (size_t)(row0 + r) * K + k0 + q * 4);
            unsigned* p = &As[r][q * 4];
            p[0] = f2tf32(v.x); p[1] = f2tf32(v.y); p[2] = f2tf32(v.z); p[3] = f2tf32(v.w);
        }
#pragma unroll
        for (int i = 0; i < 4; i++) {
            int idx = tid + i * 256;
            int kk = idx >> 5, n4 = idx & 31;
            float4 w = *reinterpret_cast<const float4*>(W + (size_t)(k0 + kk) * HH + n4 * 4);
            unsigned* p = &Ws[kk][n4 * 4];
            p[0] = f2tf32(w.x); p[1] = f2tf32(w.y); p[2] = f2tf32(w.z); p[3] = f2tf32(w.w);
        }
        __syncthreads();

#pragma unroll
        for (int k8 = 0; k8 < 4; k8++) {
            const int kk = k8 * 8;
            unsigned a[2][4], b[8][2];
#pragma unroll
            for (int mt = 0; mt < 2; mt++) {
                int r = wm * 32 + mt * 16;
                a[mt][0] = As[r + g][kk + t];
                a[mt][1] = As[r + g + 8][kk + t];
                a[mt][2] = As[r + g][kk + t + 4];
                a[mt][3] = As[r + g + 8][kk + t + 4];
            }
#pragma unroll
            for (int nt = 0; nt < 8; nt++) {
                int n = wn * 64 + nt * 8;
                b[nt][0] = Ws[kk + t][n + g];
                b[nt][1] = Ws[kk + t + 4][n + g];
            }
#pragma unroll
            for (int mt = 0; mt < 2; mt++)
#pragma unroll
                for (int nt = 0; nt < 8; nt++)
                    mma_tf32(acc[mt][nt], a[mt], b[nt]);
        }
        __syncthreads();
    }

    float csum[8][2];
#pragma unroll
    for (int nt = 0; nt < 8; nt++) { csum[nt][0] = 0.f; csum[nt][1] = 0.f; }

#pragma unroll
    for (int mt = 0; mt < 2; mt++) {
        int rr[2];
        rr[0] = row0 + wm * 32 + mt * 16 + g;
        rr[1] = rr[0] + 8;
#pragma unroll
        for (int half = 0; half < 2; half++) {
            int r = rr[half];
            if (r >= NN) continue;
            float iv = (OUTMODE == 2) ? __ldg(invdeg + r) : 1.0f;
#pragma unroll
            for (int nt = 0; nt < 8; nt++) {
                int col = wn * 64 + nt * 8 + 2 * t;
                float b0 = __ldg(bias + col), b1 = __ldg(bias + col + 1);
                float x0 = acc[mt][nt][half * 2 + 0] + b0;
                float x1 = acc[mt][nt][half * 2 + 1] + b1;
                if (LEAKY) {
                    x0 = (x0 >= 0.f) ? x0 : NEG_SLOPE * x0;
                    x1 = (x1 >= 0.f) ? x1 : NEG_SLOPE * x1;
                }
                csum[nt][0] += x0; csum[nt][1] += x1;
                if (OUTMODE == 2)
                    *reinterpret_cast<float2*>(C + (size_t)r * HH + col) = make_float2(x0, x1);
                if (OUTMODE == 1 || OUTMODE == 2) {
                    __nv_bfloat162 hb = __floats2bfloat162_rn(x0 * iv, x1 * iv);
                    *reinterpret_cast<__nv_bfloat162*>(Cb + (size_t)r * HH + col) = hb;
                }
            }
        }
    }

    __syncthreads();
#pragma unroll
    for (int nt = 0; nt < 8; nt++) {
#pragma unroll
        for (int c = 0; c < 2; c++) {
            float s = csum[nt][c];
            s += __shfl_xor_sync(0xffffffffu, s, 4);
            s += __shfl_xor_sync(0xffffffffu, s, 8);
            s += __shfl_xor_sync(0xffffffffu, s, 16);
            if (g == 0) atomicAdd(&colsm[wn * 64 + nt * 8 + 2 * t + c], s);
        }
    }
    __syncthreads();
    if (tid < HH) atomicAdd(&colsum[cs_off + tid], colsm[tid]);
}

// ---------------- final: column means -> Wpred -> Wcls -> softmax ----------------
__global__ void final_kernel(const float* __restrict__ colsum,
                             const float* __restrict__ Wpred, const float* __restrict__ bpred,
                             const float* __restrict__ Wcls, const float* __restrict__ bcls,
                             float* __restrict__ out) {
    __shared__ float cm[HH * (LL + 1)];
    __shared__ float gsh[HH];
    int tid = threadIdx.x;  // 128 threads
    for (int t = tid; t < HH * (LL + 1); t += 128) cm[t] = colsum[t] * (1.0f / (float)NN);
    __syncthreads();
    float g = bpred[tid];
    for (int k = 0; k < HH * (LL + 1); k++) g += cm[k] * Wpred[(size_t)k * HH + tid];
    gsh[tid] = g;
    __syncthreads();
    if (tid == 0) {
        float l0 = bcls[0], l1 = bcls[1];
        for (int j = 0; j < HH; j++) {
            l0 += gsh[j] * Wcls[j * 2 + 0];
            l1 += gsh[j] * Wcls[j * 2 + 1];
        }
        float m = fmaxf(l0, l1);
        float e0 = expf(l0 - m), e1 = expf(l1 - m);
        float inv = 1.0f / (e0 + e1);
        out[0] = e0 * inv;
        out[1] = e1 * inv;
    }
}

// ---------------- launch ----------------
extern "C" void kernel_launch(void* const* d_in, const int* in_sizes, int n_in,
                              void* d_out, int out_size) {
    const float* node_feat = (const float*)d_in[0];
    const float* degree    = (const float*)d_in[3];
    const float* Wn        = (const float*)d_in[4];
    const float* bn        = (const float*)d_in[5];
    const float* Wgcn      = (const float*)d_in[8];
    const float* bgcn      = (const float*)d_in[9];
    const float* Wpred     = (const float*)d_in[10];
    const float* bpred     = (const float*)d_in[11];
    const float* Wcls      = (const float*)d_in[12];
    const float* bcls      = (const float*)d_in[13];
    const int*   src       = (const int*)d_in[14];
    const int*   dst       = (const int*)d_in[15];
    float* out = (float*)d_out;

    float *p_cur, *p_agg, *p_inv, *p_cs;
    __nv_bfloat16 *p_h0b, *p_msgb;
    int *p_cnt, *p_rank, *p_rp, *p_col, *p_bsum, *p_boff;
    cudaGetSymbolAddress((void**)&p_cur,  g_cur);
    cudaGetSymbolAddress((void**)&p_agg,  g_agg);
    cudaGetSymbolAddress((void**)&p_h0b,  g_h0b);
    cudaGetSymbolAddress((void**)&p_msgb, g_msgb);
    cudaGetSymbolAddress((void**)&p_inv,  g_invdeg);
    cudaGetSymbolAddress((void**)&p_cs,   g_colsum);
    cudaGetSymbolAddress((void**)&p_cnt,  g_cnt);
    cudaGetSymbolAddress((void**)&p_rank, g_rank);
    cudaGetSymbolAddress((void**)&p_rp,   g_rowptr);
    cudaGetSymbolAddress((void**)&p_col,  g_col);
    cudaGetSymbolAddress((void**)&p_bsum, g_bsum);
    cudaGetSymbolAddress((void**)&p_boff, g_boff);

    const int gemm_blocks = (NN + 127) / 128;        // 391
    const int edge_blocks = (EE + 255) / 256;        // 3125
    const int node_blocks = NBLK;                    // 196
    const int gath_blocks = (NN * 32 + 255) / 256;   // 6250

    // 1) init counters / invdeg / colsum
    init_kernel<<<node_blocks, 256>>>(degree, p_inv, p_cnt, p_cs);

    // 2) CSR build (dst-major): hist captures ranks; scan is multi-block; fill atomic-free
    hist_kernel<<<edge_blocks, 256>>>(dst, p_cnt, p_rank);
    scan1_kernel<<<node_blocks, 256>>>(p_cnt, p_rp, p_bsum);
    scan2_kernel<<<1, 256>>>(p_bsum, p_boff, p_rp);
    scan3_kernel<<<node_blocks, 256>>>(p_rp, p_boff);
    fill_kernel<<<edge_blocks, 256>>>(src, dst, p_rp, p_rank, p_col);

    // 3) projection: h0b = bf16(node_feat @ Wn + bn) ; colsum[0:128]
    gemm_tc<NF, false, 1><<<gemm_blocks, 256>>>(node_feat, Wn, bn, nullptr, p_h0b,
                                                nullptr, p_cs, 0);

    // 4) fusion: cur[v] = sum_{u->v} h0b[u] ; msgb[v] = bf16(cur[v]*invdeg[v])
    gather_kernel<false, true><<<gath_blocks, 256>>>(p_h0b, nullptr, p_cur, p_msgb,
                                                     p_inv, p_rp, p_col);

    // 5) 3 GCN layers
    for (int l = 0; l < LL; l++) {
        // agg[v] = cur[v] + sum_{u->v} msgb[u]
        gather_kernel<true, false><<<gath_blocks, 256>>>(p_msgb, p_cur, p_agg, nullptr,
                                                         nullptr, p_rp, p_col);
        // cur = leaky(agg @ Wgcn + bgcn); msgb = bf16(cur*invdeg)  (last: colsum only)
        if (l < LL - 1)
            gemm_tc<HH, true, 2><<<gemm_blocks, 256>>>(p_agg, Wgcn, bgcn, p_cur, p_msgb,
                                                       p_inv, p_cs, (l + 1) * HH);
        else
            gemm_tc<HH, true, 0><<<gemm_blocks, 256>>>(p_agg, Wgcn, bgcn, nullptr, nullptr,
                                                       nullptr, p_cs, (l + 1) * HH);
    }

    // 6) readout
    final_kernel<<<1, 128>>>(p_cs, Wpred, bpred, Wcls, bcls, out);
}

// round 9
// speedup vs baseline: 1.5175x; 1.0484x over previous
#include <cuda_runtime.h>
#include <cuda_bf16.h>
#include <cstddef>

#define NN 50000
#define EE 800000
#define NF 256
#define HH 128
#define LL 3
#define NEG_SLOPE 0.01f
#define NBLK 196   // ceil(NN/256)

// ---------------- scratch (no allocations allowed) ----------------
__device__ float         g_cur[(size_t)NN * HH];   // current hidden h (fp32)
__device__ float         g_agg[(size_t)NN * HH];   // aggregation buffer (fp32)
__device__ __nv_bfloat16 g_h0b[(size_t)NN * HH];   // projection output (bf16)
__device__ __nv_bfloat16 g_msgb[(size_t)NN * HH];  // h*invdeg messages (bf16)
__device__ float g_invdeg[NN];
__device__ float g_colsum[HH * (LL + 1)];
__device__ int   g_cnt[NN];
__device__ int   g_rank[EE];
__device__ int   g_rowptr[NN + 1];
__device__ int   g_col[EE];                // src node per dst-sorted edge
__device__ int   g_bsum[NBLK];
__device__ int   g_boff[NBLK];

// ---------------- helpers ----------------
__device__ __forceinline__ unsigned f2tf32(float x) {
    unsigned u;
    asm("cvt.rna.tf32.f32 %0, %1;" : "=r"(u) : "f"(x));
    return u;
}

__device__ __forceinline__ void mma_tf32(float* d, const unsigned* a, const unsigned* b) {
    asm volatile(
        "mma.sync.aligned.m16n8k8.row.col.f32.tf32.tf32.f32 "
        "{%0,%1,%2,%3}, {%4,%5,%6,%7}, {%8,%9}, {%0,%1,%2,%3};\n"
        : "+f"(d[0]), "+f"(d[1]), "+f"(d[2]), "+f"(d[3])
        : "r"(a[0]), "r"(a[1]), "r"(a[2]), "r"(a[3]), "r"(b[0]), "r"(b[1]));
}

__device__ __forceinline__ void acc_bf16row(float4& acc, const __nv_bfloat16* p) {
    uint2 r = *reinterpret_cast<const uint2*>(p);
    __nv_bfloat162 b0 = *reinterpret_cast<const __nv_bfloat162*>(&r.x);
    __nv_bfloat162 b1 = *reinterpret_cast<const __nv_bfloat162*>(&r.y);
    float2 f0 = __bfloat1622float2(b0);
    float2 f1 = __bfloat1622float2(b1);
    acc.x += f0.x; acc.y += f0.y; acc.z += f1.x; acc.w += f1.y;
}

// ---------------- colsum zero (main stream, before fork) ----------------
__global__ void zero_cs_kernel(float* __restrict__ cs) {
    int i = blockIdx.x * blockDim.x + threadIdx.x;
    if (i < HH * (LL + 1)) cs[i] = 0.f;
}

// ---------------- init (s2): counters + invdeg ----------------
__global__ void init_kernel(const float* __restrict__ degree, float* __restrict__ invdeg,
                            int* __restrict__ cnt) {
    int i = blockIdx.x * blockDim.x + threadIdx.x;
    if (i < NN) {
        invdeg[i] = 1.0f / degree[i];
        cnt[i] = 0;
    }
}

// ---------------- CSR build ----------------
__global__ void hist_kernel(const int* __restrict__ dst, int* __restrict__ cnt,
                            int* __restrict__ rank) {
    int e = blockIdx.x * blockDim.x + threadIdx.x;
    if (e < EE) rank[e] = atomicAdd(&cnt[dst[e]], 1);
}

__global__ void scan1_kernel(const int* __restrict__ cnt, int* __restrict__ rowptr,
                             int* __restrict__ bsum) {
    __shared__ int ws[8];
    int tid = threadIdx.x, lane = tid & 31, wid = tid >> 5;
    int i = blockIdx.x * 256 + tid;
    int v = (i < NN) ? cnt[i] : 0;
    int x = v;
#pragma unroll
    for (int off = 1; off < 32; off <<= 1) {
        int y = __shfl_up_sync(0xffffffffu, x, off);
        if (lane >= off) x += y;
    }
    if (lane == 31) ws[wid] = x;
    __syncthreads();
    if (wid == 0 && lane < 8) {
        int s = ws[lane];
#pragma unroll
        for (int off = 1; off < 8; off <<= 1) {
            int y = __shfl_up_sync(0x000000ffu, s, off);
            if (lane >= off) s += y;
        }
        ws[lane] = s;
    }
    __syncthreads();
    int woff = wid ? ws[wid - 1] : 0;
    if (i < NN) rowptr[i] = woff + x - v;
    if (tid == 255) bsum[blockIdx.x] = woff + x;
}

__global__ void scan2_kernel(const int* __restrict__ bsum, int* __restrict__ boff,
                             int* __restrict__ rowptr) {
    __shared__ int ws[8];
    int tid = threadIdx.x, lane = tid & 31, wid = tid >> 5;
    int v = (tid < NBLK) ? bsum[tid] : 0;
    int x = v;
#pragma unroll
    for (int off = 1; off < 32; off <<= 1) {
        int y = __shfl_up_sync(0xffffffffu, x, off);
        if (lane >= off) x += y;
    }
    if (lane == 31) ws[wid] = x;
    __syncthreads();
    if (wid == 0 && lane < 8) {
        int s = ws[lane];
#pragma unroll
        for (int off = 1; off < 8; off <<= 1) {
            int y = __shfl_up_sync(0x000000ffu, s, off);
            if (lane >= off) s += y;
        }
        ws[lane] = s;
    }
    __syncthreads();
    int woff = wid ? ws[wid - 1] : 0;
    if (tid < NBLK) boff[tid] = woff + x - v;
    if (tid == 255) rowptr[NN] = woff + x;
}

__global__ void scan3_kernel(int* __restrict__ rowptr, const int* __restrict__ boff) {
    int i = blockIdx.x * 256 + threadIdx.x;
    if (i < NN) rowptr[i] += boff[blockIdx.x];
}

__global__ void fill_kernel(const int* __restrict__ src, const int* __restrict__ dst,
                            const int* __restrict__ rowptr, const int* __restrict__ rank,
                            int* __restrict__ col) {
    int e = blockIdx.x * blockDim.x + threadIdx.x;
    if (e >= EE) return;
    col[rowptr[dst[e]] + rank[e]] = src[e];
}

// ---------------- gather (bf16 messages) ----------------
template <bool ADDBASE, bool OUTB16>
__global__ __launch_bounds__(256)
void gather_kernel(const __nv_bfloat16* __restrict__ msg, const float* __restrict__ base,
                   float* __restrict__ out, __nv_bfloat16* __restrict__ outb,
                   const float* __restrict__ invdeg,
                   const int* __restrict__ rowptr, const int* __restrict__ col) {
    int node = (blockIdx.x * blockDim.x + threadIdx.x) >> 5;
    int lane = threadIdx.x & 31;
    if (node >= NN) return;
    int s0 = __ldg(rowptr + node), s1 = __ldg(rowptr + node + 1);

    float4 acc;
    if (ADDBASE)
        acc = *reinterpret_cast<const float4*>(base + (size_t)node * HH + lane * 4);
    else
        acc = make_float4(0.f, 0.f, 0.f, 0.f);

    const __nv_bfloat16* mbase = msg + lane * 4;
    int e = s0;
    for (; e + 3 < s1; e += 4) {
        int u0 = __ldg(col + e),     u1 = __ldg(col + e + 1);
        int u2 = __ldg(col + e + 2), u3 = __ldg(col + e + 3);
        acc_bf16row(acc, mbase + (size_t)u0 * HH);
        acc_bf16row(acc, mbase + (size_t)u1 * HH);
        acc_bf16row(acc, mbase + (size_t)u2 * HH);
        acc_bf16row(acc, mbase + (size_t)u3 * HH);
    }
    for (; e < s1; e++) {
        int u0 = __ldg(col + e);
        acc_bf16row(acc, mbase + (size_t)u0 * HH);
    }

    *reinterpret_cast<float4*>(out + (size_t)node * HH + lane * 4) = acc;
    if (OUTB16) {
        float iv = __ldg(invdeg + node);
        __nv_bfloat162 o0 = __floats2bfloat162_rn(acc.x * iv, acc.y * iv);
        __nv_bfloat162 o1 = __floats2bfloat162_rn(acc.z * iv, acc.w * iv);
        uint2 packed;
        packed.x = *reinterpret_cast<unsigned*>(&o0);
        packed.y = *reinterpret_cast<unsigned*>(&o1);
        *reinterpret_cast<uint2*>(outb + (size_t)node * HH + lane * 4) = packed;
    }
}

// ---------------- tf32 tensor-core GEMM ----------------
// OUTMODE: 0 = colsum only; 1 = bf16 unscaled to Cb; 2 = fp32 to C + bf16*invdeg to Cb.
template <int K, bool LEAKY, int OUTMODE>
__global__ __launch_bounds__(256, 2)
void gemm_tc(const float* __restrict__ A, const float* __restrict__ W,
             const float* __restrict__ bias, float* __restrict__ C,
             __nv_bfloat16* __restrict__ Cb, const float* __restrict__ invdeg,
             float* __restrict__ colsum, int cs_off) {
    __shared__ unsigned As[128][36];
    __shared__ unsigned Ws[32][132];
    __shared__ float colsm[HH];

    const int tid = threadIdx.x;
    const int warp = tid >> 5, lane = tid & 31;
    const int wm = warp & 3, wn = warp >> 2;
    const int g = lane >> 2, t = lane & 3;
    const int row0 = blockIdx.x * 128;

    float acc[2][8][4];
#pragma unroll
    for (int mt = 0; mt < 2; mt++)
#pragma unroll
        for (int nt = 0; nt < 8; nt++)
#pragma unroll
            for (int r = 0; r < 4; r++) acc[mt][nt][r] = 0.f;

    if (tid < HH) colsm[tid] = 0.f;

    for (int k0 = 0; k0 < K; k0 += 32) {
#pragma unroll
        for (int i = 0; i < 4; i++) {
            int idx = tid + i * 256;
            int r = idx >> 3, q = idx & 7;
            float4 v = make_float4(0.f, 0.f, 0.f, 0.f);
            if (row0 + r < NN)
                v = *reinterpret_cast<const float4*>(A + (size_t)(row0 + r) * K + k0 + q * 4);
            unsigned* p = &As[r][q * 4];
            p[0] = f2tf32(v.x); p[1] = f2tf32(v.y); p[2] = f2tf32(v.z); p[3] = f2tf32(v.w);
        }
#pragma unroll
        for (int i = 0; i < 4; i++) {
            int idx = tid + i * 256;
            int kk = idx >> 5, n4 = idx & 31;
            float4 w = *reinterpret_cast<const float4*>(W + (size_t)(k0 + kk) * HH + n4 * 4);
            unsigned* p = &Ws[kk][n4 * 4];
            p[0] = f2tf32(w.x); p[1] = f2tf32(w.y); p[2] = f2tf32(w.z); p[3] = f2tf32(w.w);
        }
        __syncthreads();

#pragma unroll
        for (int k8 = 0; k8 < 4; k8++) {
            const int kk = k8 * 8;
            unsigned a[2][4], b[8][2];
#pragma unroll
            for (int mt = 0; mt < 2; mt++) {
                int r = wm * 32 + mt * 16;
                a[mt][0] = As[r + g][kk + t];
                a[mt][1] = As[r + g + 8][kk + t];
                a[mt][2] = As[r + g][kk + t + 4];
                a[mt][3] = As[r + g + 8][kk + t + 4];
            }
#pragma unroll
            for (int nt = 0; nt < 8; nt++) {
                int n = wn * 64 + nt * 8;
                b[nt][0] = Ws[kk + t][n + g];
                b[nt][1] = Ws[kk + t + 4][n + g];
            }
#pragma unroll
            for (int mt = 0; mt < 2; mt++)
#pragma unroll
                for (int nt = 0; nt < 8; nt++)
                    mma_tf32(acc[mt][nt], a[mt], b[nt]);
        }
        __syncthreads();
    }

    float csum[8][2];
#pragma unroll
    for (int nt = 0; nt < 8; nt++) { csum[nt][0] = 0.f; csum[nt][1] = 0.f; }

#pragma unroll
    for (int mt = 0; mt < 2; mt++) {
        int rr[2];
        rr[0] = row0 + wm * 32 + mt * 16 + g;
        rr[1] = rr[0] + 8;
#pragma unroll
        for (int half = 0; half < 2; half++) {
            int r = rr[half];
            if (r >= NN) continue;
            float iv = (OUTMODE == 2) ? __ldg(invdeg + r) : 1.0f;
#pragma unroll
            for (int nt = 0; nt < 8; nt++) {
                int col = wn * 64 + nt * 8 + 2 * t;
                float b0 = __ldg(bias + col), b1 = __ldg(bias + col + 1);
                float x0 = acc[mt][nt][half * 2 + 0] + b0;
                float x1 = acc[mt][nt][half * 2 + 1] + b1;
                if (LEAKY) {
                    x0 = (x0 >= 0.f) ? x0 : NEG_SLOPE * x0;
                    x1 = (x1 >= 0.f) ? x1 : NEG_SLOPE * x1;
                }
                csum[nt][0] += x0; csum[nt][1] += x1;
                if (OUTMODE == 2)
                    *reinterpret_cast<float2*>(C + (size_t)r * HH + col) = make_float2(x0, x1);
                if (OUTMODE == 1 || OUTMODE == 2) {
                    __nv_bfloat162 hb = __floats2bfloat162_rn(x0 * iv, x1 * iv);
                    *reinterpret_cast<__nv_bfloat162*>(Cb + (size_t)r * HH + col) = hb;
                }
            }
        }
    }

    __syncthreads();
#pragma unroll
    for (int nt = 0; nt < 8; nt++) {
#pragma unroll
        for (int c = 0; c < 2; c++) {
            float s = csum[nt][c];
            s += __shfl_xor_sync(0xffffffffu, s, 4);
            s += __shfl_xor_sync(0xffffffffu, s, 8);
            s += __shfl_xor_sync(0xffffffffu, s, 16);
            if (g == 0) atomicAdd(&colsm[wn * 64 + nt * 8 + 2 * t + c], s);
        }
    }
    __syncthreads();
    if (tid < HH) atomicAdd(&colsum[cs_off + tid], colsm[tid]);
}

// ---------------- final ----------------
__global__ void final_kernel(const float* __restrict__ colsum,
                             const float* __restrict__ Wpred, const float* __restrict__ bpred,
                             const float* __restrict__ Wcls, const float* __restrict__ bcls,
                             float* __restrict__ out) {
    __shared__ float cm[HH * (LL + 1)];
    __shared__ float gsh[HH];
    int tid = threadIdx.x;  // 128 threads
    for (int t = tid; t < HH * (LL + 1); t += 128) cm[t] = colsum[t] * (1.0f / (float)NN);
    __syncthreads();
    float g = bpred[tid];
    for (int k = 0; k < HH * (LL + 1); k++) g += cm[k] * Wpred[(size_t)k * HH + tid];
    gsh[tid] = g;
    __syncthreads();
    if (tid == 0) {
        float l0 = bcls[0], l1 = bcls[1];
        for (int j = 0; j < HH; j++) {
            l0 += gsh[j] * Wcls[j * 2 + 0];
            l1 += gsh[j] * Wcls[j * 2 + 1];
        }
        float m = fmaxf(l0, l1);
        float e0 = expf(l0 - m), e1 = expf(l1 - m);
        float inv = 1.0f / (e0 + e1);
        out[0] = e0 * inv;
        out[1] = e1 * inv;
    }
}

// ---------------- launch ----------------
extern "C" void kernel_launch(void* const* d_in, const int* in_sizes, int n_in,
                              void* d_out, int out_size) {
    const float* node_feat = (const float*)d_in[0];
    const float* degree    = (const float*)d_in[3];
    const float* Wn        = (const float*)d_in[4];
    const float* bn        = (const float*)d_in[5];
    const float* Wgcn      = (const float*)d_in[8];
    const float* bgcn      = (const float*)d_in[9];
    const float* Wpred     = (const float*)d_in[10];
    const float* bpred     = (const float*)d_in[11];
    const float* Wcls      = (const float*)d_in[12];
    const float* bcls      = (const float*)d_in[13];
    const int*   src       = (const int*)d_in[14];
    const int*   dst       = (const int*)d_in[15];
    float* out = (float*)d_out;

    float *p_cur, *p_agg, *p_inv, *p_cs;
    __nv_bfloat16 *p_h0b, *p_msgb;
    int *p_cnt, *p_rank, *p_rp, *p_col, *p_bsum, *p_boff;
    cudaGetSymbolAddress((void**)&p_cur,  g_cur);
    cudaGetSymbolAddress((void**)&p_agg,  g_agg);
    cudaGetSymbolAddress((void**)&p_h0b,  g_h0b);
    cudaGetSymbolAddress((void**)&p_msgb, g_msgb);
    cudaGetSymbolAddress((void**)&p_inv,  g_invdeg);
    cudaGetSymbolAddress((void**)&p_cs,   g_colsum);
    cudaGetSymbolAddress((void**)&p_cnt,  g_cnt);
    cudaGetSymbolAddress((void**)&p_rank, g_rank);
    cudaGetSymbolAddress((void**)&p_rp,   g_rowptr);
    cudaGetSymbolAddress((void**)&p_col,  g_col);
    cudaGetSymbolAddress((void**)&p_bsum, g_bsum);
    cudaGetSymbolAddress((void**)&p_boff, g_boff);

    const int gemm_blocks = (NN + 127) / 128;        // 391
    const int edge_blocks = (EE + 255) / 256;        // 3125
    const int node_blocks = NBLK;                    // 196
    const int gath_blocks = (NN * 32 + 255) / 256;   // 6250

    // side stream + fork/join events (host objects, created once; no device alloc)
    static cudaStream_t s2 = nullptr;
    static cudaEvent_t evFork = nullptr, evJoin = nullptr;
    if (s2 == nullptr) {
        cudaStreamCreateWithFlags(&s2, cudaStreamNonBlocking);
        cudaEventCreateWithFlags(&evFork, cudaEventDisableTiming);
        cudaEventCreateWithFlags(&evJoin, cudaEventDisableTiming);
    }

    // 0) zero colsum on the MAIN stream (proj GEMM's epilogue accumulates into it)
    zero_cs_kernel<<<2, 256>>>(p_cs);

    // ---- fork ----
    cudaEventRecord(evFork, 0);
    cudaStreamWaitEvent(s2, evFork, 0);

    // s2 leg: invdeg + CSR build
    init_kernel<<<node_blocks, 256, 0, s2>>>(degree, p_inv, p_cnt);
    hist_kernel<<<edge_blocks, 256, 0, s2>>>(dst, p_cnt, p_rank);
    scan1_kernel<<<node_blocks, 256, 0, s2>>>(p_cnt, p_rp, p_bsum);
    scan2_kernel<<<1, 256, 0, s2>>>(p_bsum, p_boff, p_rp);
    scan3_kernel<<<node_blocks, 256, 0, s2>>>(p_rp, p_boff);
    fill_kernel<<<edge_blocks, 256, 0, s2>>>(src, dst, p_rp, p_rank, p_col);
    cudaEventRecord(evJoin, s2);

    // main leg: projection GEMM (independent of CSR): h0b, colsum[0:128]
    gemm_tc<NF, false, 1><<<gemm_blocks, 256>>>(node_feat, Wn, bn, nullptr, p_h0b,
                                                nullptr, p_cs, 0);

    // ---- join: fusion gather needs CSR + invdeg (s2) and h0b (main) ----
    cudaStreamWaitEvent(0, evJoin, 0);

    // fusion: cur[v] = sum_{u->v} h0b[u] ; msgb[v] = bf16(cur[v]*invdeg[v])
    gather_kernel<false, true><<<gath_blocks, 256>>>(p_h0b, nullptr, p_cur, p_msgb,
                                                     p_inv, p_rp, p_col);

    // 3 GCN layers
    for (int l = 0; l < LL; l++) {
        gather_kernel<true, false><<<gath_blocks, 256>>>(p_msgb, p_cur, p_agg, nullptr,
                                                         nullptr, p_rp, p_col);
        if (l < LL - 1)
            gemm_tc<HH, true, 2><<<gemm_blocks, 256>>>(p_agg, Wgcn, bgcn, p_cur, p_msgb,
                                                       p_inv, p_cs, (l + 1) * HH);
        else
            gemm_tc<HH, true, 0><<<gemm_blocks, 256>>>(p_agg, Wgcn, bgcn, nullptr, nullptr,
                                                       nullptr, p_cs, (l + 1) * HH);
    }

    // readout
    final_kernel<<<1, 128>>>(p_cs, Wpred, bpred, Wcls, bcls, out);
}